// round 4
// baseline (speedup 1.0000x reference)
#include <cuda_runtime.h>
#include <cstdint>

// MaxUnpooling2D: out[B,H2,W2,C] zeros except out[mask[i]] = updates[i].
// Mask indices are collision-free by construction, so no atomics: each thread
// owns 2x2 windows (per 4-channel group) and writes all 4 cells of each
// (3 zeros + the value). No zero-fill pass.
//
// R3/R4: 2 window-groups per thread with front-batched loads (MLP 4) and
// streaming cache hints (__ldcs/__stcs) — everything is touch-once.
//
// Shapes (fixed): B=16, H=W=64, C=256, up=(2,2) -> H2=W2=128.

#define B_  16
#define H_  64
#define W_  64
#define C_  256
#define H2_ 128
#define W2_ 128

#define TOTAL4   (B_ * H_ * W_ * (C_ / 4))   // 2^22 float4-groups
#define HALF4    (TOTAL4 / 2)                // 2^21

__device__ __forceinline__ unsigned out_base(unsigned t)
{
    const unsigned c4 = t & 63u;
    unsigned r = t >> 6;
    const unsigned w = r & 63u;
    r >>= 6;
    const unsigned h = r & 63u;
    const unsigned b = r >> 6;
    return (((b * H2_ + 2u * h) * W2_ + 2u * w) * C_) + 4u * c4;
}

__device__ __forceinline__ void scatter_group(
    float* __restrict__ out, unsigned base, float4 u, int4 m)
{
    // c = bits[0:8), x = bits[8:15), y = bits[15:22)  (all dims powers of 2)
    // dx = bit 8, dy = bit 15; slot k = 2*dy + dx
    const int k0 = ((m.x >> 14) & 2) | ((m.x >> 8) & 1);
    const int k1 = ((m.y >> 14) & 2) | ((m.y >> 8) & 1);
    const int k2 = ((m.z >> 14) & 2) | ((m.z >> 8) & 1);
    const int k3 = ((m.w >> 14) & 2) | ((m.w >> 8) & 1);

    float4 v0, v1, v2, v3;  // (dy,dx) = (0,0),(0,1),(1,0),(1,1)
    v0.x = (k0 == 0) ? u.x : 0.0f;  v0.y = (k1 == 0) ? u.y : 0.0f;
    v0.z = (k2 == 0) ? u.z : 0.0f;  v0.w = (k3 == 0) ? u.w : 0.0f;
    v1.x = (k0 == 1) ? u.x : 0.0f;  v1.y = (k1 == 1) ? u.y : 0.0f;
    v1.z = (k2 == 1) ? u.z : 0.0f;  v1.w = (k3 == 1) ? u.w : 0.0f;
    v2.x = (k0 == 2) ? u.x : 0.0f;  v2.y = (k1 == 2) ? u.y : 0.0f;
    v2.z = (k2 == 2) ? u.z : 0.0f;  v2.w = (k3 == 2) ? u.w : 0.0f;
    v3.x = (k0 == 3) ? u.x : 0.0f;  v3.y = (k1 == 3) ? u.y : 0.0f;
    v3.z = (k2 == 3) ? u.z : 0.0f;  v3.w = (k3 == 3) ? u.w : 0.0f;

    __stcs(reinterpret_cast<float4*>(out + base),                 v0); // (2h,  2w)
    __stcs(reinterpret_cast<float4*>(out + base + C_),            v1); // (2h,  2w+1)
    __stcs(reinterpret_cast<float4*>(out + base + W2_ * C_),      v2); // (2h+1,2w)
    __stcs(reinterpret_cast<float4*>(out + base + W2_ * C_ + C_), v3); // (2h+1,2w+1)
}

__global__ __launch_bounds__(256) void maxunpool_kernel(
    const float4* __restrict__ upd4,
    const int4*   __restrict__ msk4,
    float*        __restrict__ out)
{
    const unsigned t0 = blockIdx.x * blockDim.x + threadIdx.x;   // [0, 2^21)
    const unsigned t1 = t0 + HALF4;

    // Front-batch all four loads: 4 independent LDG.128 in flight per thread.
    const float4 u0 = __ldcs(upd4 + t0);
    const int4   m0 = __ldcs(msk4 + t0);
    const float4 u1 = __ldcs(upd4 + t1);
    const int4   m1 = __ldcs(msk4 + t1);

    scatter_group(out, out_base(t0), u0, m0);
    scatter_group(out, out_base(t1), u1, m1);
}

extern "C" void kernel_launch(void* const* d_in, const int* in_sizes, int n_in,
                              void* d_out, int out_size)
{
    const float4* upd4 = reinterpret_cast<const float4*>(d_in[0]);
    const int4*   msk4 = reinterpret_cast<const int4*>(d_in[1]);
    float*        out  = reinterpret_cast<float*>(d_out);

    const int threads = 256;
    const int blocks  = HALF4 / threads;   // 8192

    maxunpool_kernel<<<blocks, threads>>>(upd4, msk4, out);
}

// round 5
// speedup vs baseline: 1.0249x; 1.0249x over previous
#include <cuda_runtime.h>
#include <cstdint>

// MaxUnpooling2D: out[B,H2,W2,C] zeros except out[mask[i]] = updates[i].
// Mask indices are collision-free by construction, so no atomics: each thread
// owns one 2x2 window for a 4-channel group and writes all 4 cells
// (3 zeros + the value). No zero-fill pass.
//
// R5: R2 structure (1 group/thread, default loads) + __stcs stores ONLY
// (isolating the streaming-store variable after R4's bundled regression).
//
// Shapes (fixed): B=16, H=W=64, C=256, up=(2,2) -> H2=W2=128.

#define C_   256
#define W2C  32768           // W2_ * C_
#define TOTAL4 (1 << 22)     // B*H*W*(C/4) = 16*64*64*64

__global__ __launch_bounds__(256) void maxunpool_kernel(
    const float4* __restrict__ upd4,
    const int4*   __restrict__ msk4,
    float*        __restrict__ out)
{
    const unsigned t = blockIdx.x * blockDim.x + threadIdx.x;

    const float4 u = upd4[t];
    const int4   m = msk4[t];

    // t = ((b*64 + h)*64 + w)*64 + c4
    // base = (b*128 + 2h)*128*256 + (2w)*256 + 4*c4  -- all powers of 2:
    //      = (t>>18)<<22 | ((t>>12)&63)<<16 | ((t>>6)&63)<<9 | (t&63)<<2
    const unsigned base = ((t >> 18) << 22)
                        | (((t >> 12) & 63u) << 16)
                        | (((t >> 6)  & 63u) << 9)
                        | ((t & 63u) << 2);

    // mask layout: c = bits[0:8), x = bits[8:15), y = bits[15:22)
    // dx = bit 8, dy = bit 15; slot k = 2*dy + dx
    const int k0 = ((m.x >> 14) & 2) | ((m.x >> 8) & 1);
    const int k1 = ((m.y >> 14) & 2) | ((m.y >> 8) & 1);
    const int k2 = ((m.z >> 14) & 2) | ((m.z >> 8) & 1);
    const int k3 = ((m.w >> 14) & 2) | ((m.w >> 8) & 1);

    float4 v0, v1, v2, v3;  // (dy,dx) = (0,0),(0,1),(1,0),(1,1)
    v0.x = (k0 == 0) ? u.x : 0.0f;  v0.y = (k1 == 0) ? u.y : 0.0f;
    v0.z = (k2 == 0) ? u.z : 0.0f;  v0.w = (k3 == 0) ? u.w : 0.0f;
    v1.x = (k0 == 1) ? u.x : 0.0f;  v1.y = (k1 == 1) ? u.y : 0.0f;
    v1.z = (k2 == 1) ? u.z : 0.0f;  v1.w = (k3 == 1) ? u.w : 0.0f;
    v2.x = (k0 == 2) ? u.x : 0.0f;  v2.y = (k1 == 2) ? u.y : 0.0f;
    v2.z = (k2 == 2) ? u.z : 0.0f;  v2.w = (k3 == 2) ? u.w : 0.0f;
    v3.x = (k0 == 3) ? u.x : 0.0f;  v3.y = (k1 == 3) ? u.y : 0.0f;
    v3.z = (k2 == 3) ? u.z : 0.0f;  v3.w = (k3 == 3) ? u.w : 0.0f;

    __stcs(reinterpret_cast<float4*>(out + base),             v0); // (2h,  2w)
    __stcs(reinterpret_cast<float4*>(out + base + C_),        v1); // (2h,  2w+1)
    __stcs(reinterpret_cast<float4*>(out + base + W2C),       v2); // (2h+1,2w)
    __stcs(reinterpret_cast<float4*>(out + base + W2C + C_),  v3); // (2h+1,2w+1)
}

extern "C" void kernel_launch(void* const* d_in, const int* in_sizes, int n_in,
                              void* d_out, int out_size)
{
    const float4* upd4 = reinterpret_cast<const float4*>(d_in[0]);
    const int4*   msk4 = reinterpret_cast<const int4*>(d_in[1]);
    float*        out  = reinterpret_cast<float*>(d_out);

    const int threads = 256;
    const int blocks  = TOTAL4 / threads;   // 16384

    maxunpool_kernel<<<blocks, threads>>>(upd4, msk4, out);
}